// round 1
// baseline (speedup 1.0000x reference)
#include <cuda_runtime.h>
#include <math.h>

// Problem dims (fixed by the dataset)
#define B_  32
#define NP_ 2048
#define NG_ 2048
#define L_  256
#define BIGF 1e18f
#define EPSF 1e-6f

#define LAMBDA_E_SUM      10.0f
#define LAMBDA_HIT        20.0f
#define LAMBDA_CHAMFER    0.001f
#define LAMBDA_HIT_ENTROPY 0.1f

// Scratch (no allocation allowed -> device globals)
__device__ float4 g_pred[B_ * NP_];  // {-2x, -2y, -2z, |p|^2}
__device__ float4 g_tgt [B_ * NG_];  // { x,   y,   z,  |t|^2 + (mask?0:BIG)}
// accumulators:
// 0: sum min_dist_pred (clamped)      1: sum |predE - matchedE|
// 2: sum min_dist_target*mask         3: entropy sum (already negated)
// 4: kld inner sum                    5: total mask sum
// 6: sum_b (nhits_pred-nhits_tgt)^2   7: sum_b (totE - e_init)^2
__device__ float g_acc[8];

// ---------------------------------------------------------------------------
__device__ __forceinline__ float blockReduceSum(float v, float* sh) {
    const unsigned full = 0xffffffffu;
    #pragma unroll
    for (int o = 16; o > 0; o >>= 1) v += __shfl_down_sync(full, v, o);
    int w = threadIdx.x >> 5;
    int l = threadIdx.x & 31;
    __syncthreads();                 // protect sh reuse across calls
    if (l == 0) sh[w] = v;
    __syncthreads();
    if (threadIdx.x < 32) {
        v = (threadIdx.x < (blockDim.x >> 5)) ? sh[threadIdx.x] : 0.0f;
        #pragma unroll
        for (int o = 16; o > 0; o >>= 1) v += __shfl_down_sync(full, v, o);
    }
    return v;  // valid in thread 0
}

// ---------------------------------------------------------------------------
__global__ void init_kernel() {
    if (threadIdx.x < 8) g_acc[threadIdx.x] = 0.0f;
}

// One block per batch: pack points, and do all the cheap reductions.
__global__ void prep_kernel(const float* __restrict__ preds,
                            const float* __restrict__ target,
                            const float* __restrict__ mask,
                            const float* __restrict__ mu,
                            const float* __restrict__ logvar,
                            const float* __restrict__ e_init) {
    __shared__ float shr[8];
    int b = blockIdx.x;
    int tid = threadIdx.x;

    const float* pb = preds  + (size_t)b * 5 * NP_;
    const float* tb = target + (size_t)b * 4 * NG_;
    const float* mb = mask   + (size_t)b * NG_;

    float nhp = 0.f, teh = 0.f, nht = 0.f, ent = 0.f, kld = 0.f;

    for (int n = tid; n < NP_; n += 256) {
        float x = pb[n], y = pb[NP_ + n], z = pb[2 * NP_ + n];
        float E = pb[3 * NP_ + n], h = pb[4 * NP_ + n];
        g_pred[b * NP_ + n] = make_float4(-2.f * x, -2.f * y, -2.f * z,
                                          x * x + y * y + z * z);
        nhp += h;
        teh += E * h;
        ent += -(h * logf(h + EPSF) + (1.f - h) * logf(1.f - h + EPSF));
    }
    for (int m = tid; m < NG_; m += 256) {
        float x = tb[m], y = tb[NG_ + m], z = tb[2 * NG_ + m];
        float mk = mb[m];
        float tn = x * x + y * y + z * z;
        g_tgt[b * NG_ + m] = make_float4(x, y, z, tn + (mk == 0.f ? BIGF : 0.f));
        nht += mk;
    }
    const float* mub = mu + b * L_;
    const float* lvb = logvar + b * L_;
    for (int i = tid; i < L_; i += 256) {
        float m_ = mub[i], lv = lvb[i];
        kld += 1.f + lv - m_ * m_ - expf(lv);
    }

    nhp = blockReduceSum(nhp, shr);
    teh = blockReduceSum(teh, shr);
    nht = blockReduceSum(nht, shr);
    ent = blockReduceSum(ent, shr);
    kld = blockReduceSum(kld, shr);

    if (tid == 0) {
        atomicAdd(&g_acc[3], ent);
        atomicAdd(&g_acc[4], kld);
        atomicAdd(&g_acc[5], nht);
        float dh = nhp - nht;
        atomicAdd(&g_acc[6], dh * dh);
        float de = teh - e_init[b];
        atomicAdd(&g_acc[7], de * de);
    }
}

// ---------------------------------------------------------------------------
// Pass 1: per pred point, min/argmin over masked targets. 128 blocks x 256 thr,
// 2 preds per thread. Full target tile (32KB) staged in shared once.
__global__ __launch_bounds__(256) void pass1_kernel(
    const float* __restrict__ preds, const float* __restrict__ target) {
    __shared__ float4 sh[NG_];
    __shared__ float shr[8];

    int b = blockIdx.x >> 2;       // 4 tiles/batch
    int tile = blockIdx.x & 3;
    int tid = threadIdx.x;

    const float4* tg = g_tgt + b * NG_;
    for (int m = tid; m < NG_; m += 256) sh[m] = tg[m];
    __syncthreads();

    int n0 = tile * 512 + tid;
    int n1 = n0 + 256;
    float4 a0 = g_pred[b * NP_ + n0];
    float4 a1 = g_pred[b * NP_ + n1];

    float best0 = 3.4e38f, best1 = 3.4e38f;
    int i0 = 0, i1 = 0;

    #pragma unroll 4
    for (int m = 0; m < NG_; ++m) {
        float4 t = sh[m];
        float v0 = fmaf(a0.x, t.x, fmaf(a0.y, t.y, fmaf(a0.z, t.z, t.w)));
        float v1 = fmaf(a1.x, t.x, fmaf(a1.y, t.y, fmaf(a1.z, t.z, t.w)));
        if (v0 < best0) { best0 = v0; i0 = m; }
        if (v1 < best1) { best1 = v1; i1 = m; }
    }

    const float* tE = target + (size_t)b * 4 * NG_ + 3 * NG_;
    const float* pE = preds  + (size_t)b * 5 * NP_ + 3 * NP_;

    float md = fmaxf(a0.w + best0, 0.f) + fmaxf(a1.w + best1, 0.f);
    float le = fabsf(pE[n0] - tE[i0]) + fabsf(pE[n1] - tE[i1]);

    md = blockReduceSum(md, shr);
    le = blockReduceSum(le, shr);
    if (tid == 0) {
        atomicAdd(&g_acc[0], md);
        atomicAdd(&g_acc[1], le);
    }
}

// Pass 2: per target point, min over preds (no argmin). Symmetric layout.
__global__ __launch_bounds__(256) void pass2_kernel(
    const float* __restrict__ mask) {
    __shared__ float4 sh[NP_];
    __shared__ float shr[8];

    int b = blockIdx.x >> 2;
    int tile = blockIdx.x & 3;
    int tid = threadIdx.x;

    const float4* pr = g_pred + b * NP_;
    for (int n = tid; n < NP_; n += 256) sh[n] = pr[n];
    __syncthreads();

    int m0 = tile * 512 + tid;
    int m1 = m0 + 256;
    float4 t0 = g_tgt[b * NG_ + m0];
    float4 t1 = g_tgt[b * NG_ + m1];

    float best0 = 3.4e38f, best1 = 3.4e38f;

    #pragma unroll 4
    for (int n = 0; n < NP_; ++n) {
        float4 p = sh[n];
        float v0 = fmaf(t0.x, p.x, fmaf(t0.y, p.y, fmaf(t0.z, p.z, p.w)));
        float v1 = fmaf(t1.x, p.x, fmaf(t1.y, p.y, fmaf(t1.z, p.z, p.w)));
        best0 = fminf(best0, v0);
        best1 = fminf(best1, v1);
    }

    float tn0 = t0.x * t0.x + t0.y * t0.y + t0.z * t0.z;
    float tn1 = t1.x * t1.x + t1.y * t1.y + t1.z * t1.z;
    float mk0 = mask[(size_t)b * NG_ + m0];
    float mk1 = mask[(size_t)b * NG_ + m1];
    float s = fmaxf(tn0 + best0, 0.f) * mk0 + fmaxf(tn1 + best1, 0.f) * mk1;

    s = blockReduceSum(s, shr);
    if (tid == 0) atomicAdd(&g_acc[2], s);
}

// ---------------------------------------------------------------------------
__global__ void final_kernel(const float* __restrict__ kl_weight,
                             float* __restrict__ out, int out_size) {
    float chamP = g_acc[0] / (float)(B_ * NP_);
    float chamT = g_acc[2] / g_acc[5];
    float loss_chamf = (chamT + chamP) * LAMBDA_CHAMFER;
    float localE = g_acc[1] / (float)(B_ * NP_);
    float ge  = LAMBDA_E_SUM * g_acc[7] / (float)B_;
    float hit = LAMBDA_HIT   * g_acc[6] / (float)B_;
    float entr = LAMBDA_HIT_ENTROPY * g_acc[3] / (float)(B_ * NP_);
    float kld = kl_weight[0] * (-0.5f * g_acc[4] / (float)B_);
    float total = loss_chamf + localE + kld + ge + hit + entr;

    if (out_size >= 6) {
        out[0] = total;
        out[1] = loss_chamf;
        out[2] = localE;
        out[3] = ge;
        out[4] = hit;
        out[5] = kld;
    } else if (out_size == 5) {
        out[0] = loss_chamf; out[1] = localE; out[2] = ge;
        out[3] = hit;        out[4] = kld;
    } else {
        out[0] = total;
    }
}

// ---------------------------------------------------------------------------
extern "C" void kernel_launch(void* const* d_in, const int* in_sizes, int n_in,
                              void* d_out, int out_size) {
    const float* preds   = (const float*)d_in[0];
    const float* target  = (const float*)d_in[1];
    const float* tmask   = (const float*)d_in[2];
    const float* mu      = (const float*)d_in[3];
    const float* logvar  = (const float*)d_in[4];
    const float* e_init  = (const float*)d_in[5];
    const float* klw     = (const float*)d_in[6];
    float* out = (float*)d_out;

    init_kernel<<<1, 32>>>();
    prep_kernel<<<B_, 256>>>(preds, target, tmask, mu, logvar, e_init);
    pass1_kernel<<<B_ * 4, 256>>>(preds, target);
    pass2_kernel<<<B_ * 4, 256>>>(tmask);
    final_kernel<<<1, 1>>>(klw, out, out_size);
}

// round 2
// speedup vs baseline: 1.2086x; 1.2086x over previous
#include <cuda_runtime.h>
#include <math.h>

#define B_  32
#define NP_ 2048
#define NG_ 2048
#define L_  256
#define BIGF 1e18f
#define EPSF 1e-6f

#define LAMBDA_E_SUM       10.0f
#define LAMBDA_HIT         20.0f
#define LAMBDA_CHAMFER     0.001f
#define LAMBDA_HIT_ENTROPY 0.1f

typedef unsigned long long ull;

// ---------------- device scratch (no allocation allowed) -------------------
// Paired (interleaved) layouts for packed f32x2 math:
//   predPA[jp] = {-2x0,-2x1,-2y0,-2y1}   predPB[jp] = {-2z0,-2z1, pn0, pn1}
//   tgtPA [jp] = {  x0,  x1,  y0,  y1}   tgtPB [jp] = {  z0,  z1, w0m, w1m}  (w = tn + BIG*!mask)
__device__ float4 g_predPA[B_ * NP_ / 2];
__device__ float4 g_predPB[B_ * NP_ / 2];
__device__ float4 g_tgtPA [B_ * NG_ / 2];
__device__ float4 g_tgtPB [B_ * NG_ / 2];
// Scalar per-point layouts:
__device__ float4 g_predS[B_ * NP_];   // {-2x,-2y,-2z, pn}
__device__ float4 g_tgtS [B_ * NG_];   // {  x,  y,  z, tn}  (unmasked)
// Partial results (4 chunks of the reduced dimension each):
__device__ float g_best1[4][B_ * NP_];
__device__ int   g_idx1 [4][B_ * NP_];
__device__ float g_best2[4][B_ * NG_];
// accumulators:
// 0 sum min_dist_pred   1 sum |pE - matched tE|   2 sum min_dist_tgt*mask
// 3 entropy sum         4 kld inner sum           5 mask sum
// 6 sum (dhits)^2       7 sum (dE)^2
__device__ float g_acc[8];

// ---------------------------------------------------------------------------
__device__ __forceinline__ ull fma2(ull a, ull b, ull c) {
    ull d;
    asm("fma.rn.f32x2 %0, %1, %2, %3;" : "=l"(d) : "l"(a), "l"(b), "l"(c));
    return d;
}
__device__ __forceinline__ ull dup2(float x) {
    ull d;
    asm("mov.b64 %0, {%1, %1};" : "=l"(d) : "f"(x));
    return d;
}
__device__ __forceinline__ float2 unpack2(ull v) {
    float2 r;
    asm("mov.b64 {%0, %1}, %2;" : "=f"(r.x), "=f"(r.y) : "l"(v));
    return r;
}

__device__ __forceinline__ float blockReduceSum(float v, float* sh) {
    const unsigned full = 0xffffffffu;
    #pragma unroll
    for (int o = 16; o > 0; o >>= 1) v += __shfl_down_sync(full, v, o);
    int w = threadIdx.x >> 5, l = threadIdx.x & 31;
    __syncthreads();
    if (l == 0) sh[w] = v;
    __syncthreads();
    if (threadIdx.x < 32) {
        v = (threadIdx.x < (blockDim.x >> 5)) ? sh[threadIdx.x] : 0.0f;
        #pragma unroll
        for (int o = 16; o > 0; o >>= 1) v += __shfl_down_sync(full, v, o);
    }
    return v;
}

// ---------------------------------------------------------------------------
__global__ void init_kernel() {
    if (threadIdx.x < 8) g_acc[threadIdx.x] = 0.0f;
}

// One block per batch: build all packed layouts + cheap reductions.
__global__ void prep_kernel(const float* __restrict__ preds,
                            const float* __restrict__ target,
                            const float* __restrict__ mask,
                            const float* __restrict__ mu,
                            const float* __restrict__ logvar,
                            const float* __restrict__ e_init) {
    __shared__ float shr[8];
    int b = blockIdx.x, tid = threadIdx.x;
    const float* pb = preds  + (size_t)b * 5 * NP_;
    const float* tb = target + (size_t)b * 4 * NG_;
    const float* mb = mask   + (size_t)b * NG_;

    float nhp = 0.f, teh = 0.f, nht = 0.f, ent = 0.f, kld = 0.f;

    for (int jp = tid; jp < NP_ / 2; jp += 256) {
        int n = 2 * jp;
        float2 x = *(const float2*)(pb + n);
        float2 y = *(const float2*)(pb + NP_ + n);
        float2 z = *(const float2*)(pb + 2 * NP_ + n);
        float2 E = *(const float2*)(pb + 3 * NP_ + n);
        float2 h = *(const float2*)(pb + 4 * NP_ + n);
        float pn0 = x.x * x.x + y.x * y.x + z.x * z.x;
        float pn1 = x.y * x.y + y.y * y.y + z.y * z.y;
        g_predPA[b * 1024 + jp] = make_float4(-2.f * x.x, -2.f * x.y, -2.f * y.x, -2.f * y.y);
        g_predPB[b * 1024 + jp] = make_float4(-2.f * z.x, -2.f * z.y, pn0, pn1);
        g_predS[b * NP_ + n]     = make_float4(-2.f * x.x, -2.f * y.x, -2.f * z.x, pn0);
        g_predS[b * NP_ + n + 1] = make_float4(-2.f * x.y, -2.f * y.y, -2.f * z.y, pn1);
        nhp += h.x + h.y;
        teh += E.x * h.x + E.y * h.y;
        ent += -(h.x * logf(h.x + EPSF) + (1.f - h.x) * logf(1.f - h.x + EPSF))
               -(h.y * logf(h.y + EPSF) + (1.f - h.y) * logf(1.f - h.y + EPSF));

        float2 tx = *(const float2*)(tb + n);
        float2 ty = *(const float2*)(tb + NG_ + n);
        float2 tz = *(const float2*)(tb + 2 * NG_ + n);
        float2 mk = *(const float2*)(mb + n);
        float tn0 = tx.x * tx.x + ty.x * ty.x + tz.x * tz.x;
        float tn1 = tx.y * tx.y + ty.y * ty.y + tz.y * tz.y;
        float w0 = tn0 + (mk.x == 0.f ? BIGF : 0.f);
        float w1 = tn1 + (mk.y == 0.f ? BIGF : 0.f);
        g_tgtPA[b * 1024 + jp] = make_float4(tx.x, tx.y, ty.x, ty.y);
        g_tgtPB[b * 1024 + jp] = make_float4(tz.x, tz.y, w0, w1);
        g_tgtS[b * NG_ + n]     = make_float4(tx.x, ty.x, tz.x, tn0);
        g_tgtS[b * NG_ + n + 1] = make_float4(tx.y, ty.y, tz.y, tn1);
        nht += mk.x + mk.y;
    }
    const float* mub = mu + b * L_;
    const float* lvb = logvar + b * L_;
    for (int i = tid; i < L_; i += 256) {
        float m_ = mub[i], lv = lvb[i];
        kld += 1.f + lv - m_ * m_ - expf(lv);
    }

    nhp = blockReduceSum(nhp, shr);
    teh = blockReduceSum(teh, shr);
    nht = blockReduceSum(nht, shr);
    ent = blockReduceSum(ent, shr);
    kld = blockReduceSum(kld, shr);
    if (tid == 0) {
        atomicAdd(&g_acc[3], ent);
        atomicAdd(&g_acc[4], kld);
        atomicAdd(&g_acc[5], nht);
        float dh = nhp - nht; atomicAdd(&g_acc[6], dh * dh);
        float de = teh - e_init[b]; atomicAdd(&g_acc[7], de * de);
    }
}

// ---------------------------------------------------------------------------
// Pass 1: min/argmin over masked targets for each pred point.
// Grid 256: b = blk>>3, point-tile (2 of 1024), target-chunk (4 of 512).
__global__ __launch_bounds__(256) void pass1_kernel() {
    __shared__ ulonglong2 shA[256], shB[256];
    int blk = blockIdx.x, tid = threadIdx.x;
    int b = blk >> 3, sub = blk & 7;
    int pt = sub >> 2, tc = sub & 3;

    {
        float4 a = g_tgtPA[b * 1024 + tc * 256 + tid];
        float4 v = g_tgtPB[b * 1024 + tc * 256 + tid];
        shA[tid] = *(ulonglong2*)&a;
        shB[tid] = *(ulonglong2*)&v;
    }
    __syncthreads();

    int pbase = b * NP_ + pt * 1024 + tid;
    ull ax2[4], ay2[4], az2[4];
    #pragma unroll
    for (int i = 0; i < 4; i++) {
        float4 p = g_predS[pbase + i * 256];
        ax2[i] = dup2(p.x); ay2[i] = dup2(p.y); az2[i] = dup2(p.z);
    }
    float bl[4], bh[4]; int il[4], ih[4];
    #pragma unroll
    for (int i = 0; i < 4; i++) { bl[i] = 3.4e38f; bh[i] = 3.4e38f; il[i] = 0; ih[i] = 0; }

    #pragma unroll 2
    for (int j = 0; j < 256; j++) {
        ulonglong2 A = shA[j], Bv = shB[j];
        #pragma unroll
        for (int i = 0; i < 4; i++) {
            ull t = fma2(az2[i], Bv.x, Bv.y);
            t = fma2(ay2[i], A.y, t);
            t = fma2(ax2[i], A.x, t);
            float2 v = unpack2(t);
            bool p0 = v.x < bl[i];
            bl[i] = fminf(bl[i], v.x);
            il[i] = p0 ? j : il[i];
            bool p1 = v.y < bh[i];
            bh[i] = fminf(bh[i], v.y);
            ih[i] = p1 ? j : ih[i];
        }
    }
    #pragma unroll
    for (int i = 0; i < 4; i++) {
        float best = bl[i]; int idx = 2 * il[i];
        if (bh[i] < best) { best = bh[i]; idx = 2 * ih[i] + 1; }
        int gp = pbase + i * 256;
        g_best1[tc][gp] = best;
        g_idx1[tc][gp] = tc * 512 + idx;
    }
}

// Pass 2: min over preds for each target point (no argmin, no mask).
__global__ __launch_bounds__(256) void pass2_kernel() {
    __shared__ ulonglong2 shA[256], shB[256];
    int blk = blockIdx.x, tid = threadIdx.x;
    int b = blk >> 3, sub = blk & 7;
    int tt = sub >> 2, pc = sub & 3;

    {
        float4 a = g_predPA[b * 1024 + pc * 256 + tid];
        float4 v = g_predPB[b * 1024 + pc * 256 + tid];
        shA[tid] = *(ulonglong2*)&a;
        shB[tid] = *(ulonglong2*)&v;
    }
    __syncthreads();

    int tbase = b * NG_ + tt * 1024 + tid;
    ull tx2[4], ty2[4], tz2[4];
    #pragma unroll
    for (int i = 0; i < 4; i++) {
        float4 t = g_tgtS[tbase + i * 256];
        tx2[i] = dup2(t.x); ty2[i] = dup2(t.y); tz2[i] = dup2(t.z);
    }
    float bl[4], bh[4];
    #pragma unroll
    for (int i = 0; i < 4; i++) { bl[i] = 3.4e38f; bh[i] = 3.4e38f; }

    #pragma unroll 2
    for (int j = 0; j < 256; j++) {
        ulonglong2 A = shA[j], Bv = shB[j];
        #pragma unroll
        for (int i = 0; i < 4; i++) {
            ull t = fma2(tz2[i], Bv.x, Bv.y);
            t = fma2(ty2[i], A.y, t);
            t = fma2(tx2[i], A.x, t);
            float2 v = unpack2(t);
            bl[i] = fminf(bl[i], v.x);
            bh[i] = fminf(bh[i], v.y);
        }
    }
    #pragma unroll
    for (int i = 0; i < 4; i++)
        g_best2[pc][tbase + i * 256] = fminf(bl[i], bh[i]);
}

// ---------------------------------------------------------------------------
// Combine partials: blocks 0..127 -> preds, 128..255 -> targets.
__global__ __launch_bounds__(256) void combine_kernel(
    const float* __restrict__ preds, const float* __restrict__ target,
    const float* __restrict__ mask) {
    __shared__ float shr[8];
    int blk = blockIdx.x, tid = threadIdx.x;

    if (blk < 128) {
        float md = 0.f, le = 0.f;
        #pragma unroll
        for (int r = 0; r < 2; r++) {
            int n = blk * 512 + r * 256 + tid;
            float best = g_best1[0][n]; int idx = g_idx1[0][n];
            #pragma unroll
            for (int s = 1; s < 4; s++) {
                float v = g_best1[s][n]; int ix = g_idx1[s][n];
                if (v < best) { best = v; idx = ix; }
            }
            int b = n >> 11, nn = n & (NP_ - 1);
            float pn = g_predS[n].w;
            md += fmaxf(pn + best, 0.f);
            float tE = target[(size_t)b * 4 * NG_ + 3 * NG_ + idx];
            float pE = preds[(size_t)b * 5 * NP_ + 3 * NP_ + nn];
            le += fabsf(pE - tE);
        }
        md = blockReduceSum(md, shr);
        le = blockReduceSum(le, shr);
        if (tid == 0) { atomicAdd(&g_acc[0], md); atomicAdd(&g_acc[1], le); }
    } else {
        float s = 0.f;
        #pragma unroll
        for (int r = 0; r < 2; r++) {
            int m = (blk - 128) * 512 + r * 256 + tid;
            float best = g_best2[0][m];
            #pragma unroll
            for (int c = 1; c < 4; c++) best = fminf(best, g_best2[c][m]);
            float tn = g_tgtS[m].w;
            float mk = mask[m];
            s += fmaxf(tn + best, 0.f) * mk;
        }
        s = blockReduceSum(s, shr);
        if (tid == 0) atomicAdd(&g_acc[2], s);
    }
}

// ---------------------------------------------------------------------------
__global__ void final_kernel(const float* __restrict__ kl_weight,
                             float* __restrict__ out, int out_size) {
    float chamP = g_acc[0] / (float)(B_ * NP_);
    float chamT = g_acc[2] / g_acc[5];
    float loss_chamf = (chamT + chamP) * LAMBDA_CHAMFER;
    float localE = g_acc[1] / (float)(B_ * NP_);
    float ge   = LAMBDA_E_SUM * g_acc[7] / (float)B_;
    float hit  = LAMBDA_HIT   * g_acc[6] / (float)B_;
    float entr = LAMBDA_HIT_ENTROPY * g_acc[3] / (float)(B_ * NP_);
    float kld  = kl_weight[0] * (-0.5f * g_acc[4] / (float)B_);
    float total = loss_chamf + localE + kld + ge + hit + entr;

    if (out_size >= 6) {
        out[0] = total;
        out[1] = loss_chamf;
        out[2] = localE;
        out[3] = ge;
        out[4] = hit;
        out[5] = kld;
    } else if (out_size == 5) {
        out[0] = loss_chamf; out[1] = localE; out[2] = ge;
        out[3] = hit;        out[4] = kld;
    } else {
        out[0] = total;
    }
}

// ---------------------------------------------------------------------------
extern "C" void kernel_launch(void* const* d_in, const int* in_sizes, int n_in,
                              void* d_out, int out_size) {
    const float* preds  = (const float*)d_in[0];
    const float* target = (const float*)d_in[1];
    const float* tmask  = (const float*)d_in[2];
    const float* mu     = (const float*)d_in[3];
    const float* logvar = (const float*)d_in[4];
    const float* e_init = (const float*)d_in[5];
    const float* klw    = (const float*)d_in[6];
    float* out = (float*)d_out;

    init_kernel<<<1, 32>>>();
    prep_kernel<<<B_, 256>>>(preds, target, tmask, mu, logvar, e_init);
    pass1_kernel<<<256, 256>>>();
    pass2_kernel<<<256, 256>>>();
    combine_kernel<<<256, 256>>>(preds, target, tmask);
    final_kernel<<<1, 1>>>(klw, out, out_size);
}

// round 3
// speedup vs baseline: 1.5166x; 1.2548x over previous
#include <cuda_runtime.h>
#include <math.h>

#define B_  32
#define NP_ 2048
#define NG_ 2048
#define L_  256
#define BIGF 1e18f
#define EPSF 1e-6f

#define LAMBDA_E_SUM       10.0f
#define LAMBDA_HIT         20.0f
#define LAMBDA_CHAMFER     0.001f
#define LAMBDA_HIT_ENTROPY 0.1f

typedef unsigned long long ull;

// ---------------- device scratch ----------------
// Packed pair layouts:
//   PA[jp] = {c0_0, c0_1, c1_0, c1_1}  PB[jp] = {c2_0, c2_1, w_0, w_1}
// pred packed: c = -2*xyz, w = |p|^2 ; tgt packed: c = xyz, w = |t|^2 + BIG*!mask
__device__ float4 g_predPA[B_ * NP_ / 2];
__device__ float4 g_predPB[B_ * NP_ / 2];
__device__ float4 g_tgtPA [B_ * NG_ / 2];
__device__ float4 g_tgtPB [B_ * NG_ / 2];
// Scalar per-point layouts:
__device__ float4 g_predS[B_ * NP_];   // {-2x,-2y,-2z, pn}
__device__ float4 g_tgtS [B_ * NG_];   // {  x,  y,  z, tn}
// Partial minima, 8 reduction-chunks each. pass1 values carry the chunk-local
// index embedded in the low 8 mantissa bits.
__device__ float g_best1[8][B_ * NP_];
__device__ float g_best2[8][B_ * NG_];
// accumulators: 0 sum minD_pred  1 sum|dE|  2 sum minD_tgt*mask
//               3 entropy  4 kld  5 mask sum
__device__ float g_acc[8];
__device__ float g_bat[B_ * 4];   // per-batch: nhp, teh, nht, pad

// ---------------------------------------------------------------------------
__device__ __forceinline__ ull fma2(ull a, ull b, ull c) {
    ull d;
    asm("fma.rn.f32x2 %0, %1, %2, %3;" : "=l"(d) : "l"(a), "l"(b), "l"(c));
    return d;
}
__device__ __forceinline__ ull dup2(float x) {
    ull d;
    asm("mov.b64 %0, {%1, %1};" : "=l"(d) : "f"(x));
    return d;
}
__device__ __forceinline__ float2 unpack2(ull v) {
    float2 r;
    asm("mov.b64 {%0, %1}, %2;" : "=f"(r.x), "=f"(r.y) : "l"(v));
    return r;
}

__device__ __forceinline__ float blockReduceSum(float v, float* sh) {
    const unsigned full = 0xffffffffu;
    #pragma unroll
    for (int o = 16; o > 0; o >>= 1) v += __shfl_down_sync(full, v, o);
    int w = threadIdx.x >> 5, l = threadIdx.x & 31;
    __syncthreads();
    if (l == 0) sh[w] = v;
    __syncthreads();
    if (threadIdx.x < 32) {
        v = (threadIdx.x < (blockDim.x >> 5)) ? sh[threadIdx.x] : 0.0f;
        #pragma unroll
        for (int o = 16; o > 0; o >>= 1) v += __shfl_down_sync(full, v, o);
    }
    return v;
}

// ---------------------------------------------------------------------------
__global__ void init_kernel() {
    int t = threadIdx.x;
    if (t < 8) g_acc[t] = 0.0f;
    if (t < B_ * 4) g_bat[t] = 0.0f;
}

// 128 blocks: b = blk>>2, segment of 256 packed pairs. 1 pair/thread.
__global__ __launch_bounds__(256) void prep_kernel(
    const float* __restrict__ preds, const float* __restrict__ target,
    const float* __restrict__ mask,  const float* __restrict__ mu,
    const float* __restrict__ logvar) {
    __shared__ float shr[8];
    int blk = blockIdx.x, tid = threadIdx.x;
    int b = blk >> 2, seg = blk & 3;
    int jp = seg * 256 + tid;        // packed pair index in [0, 1024)
    int n = 2 * jp;

    const float* pb = preds  + (size_t)b * 5 * NP_;
    const float* tb = target + (size_t)b * 4 * NG_;
    const float* mb = mask   + (size_t)b * NG_;

    float2 x = *(const float2*)(pb + n);
    float2 y = *(const float2*)(pb + NP_ + n);
    float2 z = *(const float2*)(pb + 2 * NP_ + n);
    float2 E = *(const float2*)(pb + 3 * NP_ + n);
    float2 h = *(const float2*)(pb + 4 * NP_ + n);
    float pn0 = x.x * x.x + y.x * y.x + z.x * z.x;
    float pn1 = x.y * x.y + y.y * y.y + z.y * z.y;
    g_predPA[b * 1024 + jp] = make_float4(-2.f * x.x, -2.f * x.y, -2.f * y.x, -2.f * y.y);
    g_predPB[b * 1024 + jp] = make_float4(-2.f * z.x, -2.f * z.y, pn0, pn1);
    g_predS[b * NP_ + n]     = make_float4(-2.f * x.x, -2.f * y.x, -2.f * z.x, pn0);
    g_predS[b * NP_ + n + 1] = make_float4(-2.f * x.y, -2.f * y.y, -2.f * z.y, pn1);
    float nhp = h.x + h.y;
    float teh = E.x * h.x + E.y * h.y;
    float ent = -(h.x * __logf(h.x + EPSF) + (1.f - h.x) * __logf(1.f - h.x + EPSF))
                -(h.y * __logf(h.y + EPSF) + (1.f - h.y) * __logf(1.f - h.y + EPSF));

    float2 tx = *(const float2*)(tb + n);
    float2 ty = *(const float2*)(tb + NG_ + n);
    float2 tz = *(const float2*)(tb + 2 * NG_ + n);
    float2 mk = *(const float2*)(mb + n);
    float tn0 = tx.x * tx.x + ty.x * ty.x + tz.x * tz.x;
    float tn1 = tx.y * tx.y + ty.y * ty.y + tz.y * tz.y;
    g_tgtPA[b * 1024 + jp] = make_float4(tx.x, tx.y, ty.x, ty.y);
    g_tgtPB[b * 1024 + jp] = make_float4(tz.x, tz.y,
                                         tn0 + (mk.x == 0.f ? BIGF : 0.f),
                                         tn1 + (mk.y == 0.f ? BIGF : 0.f));
    g_tgtS[b * NG_ + n]     = make_float4(tx.x, ty.x, tz.x, tn0);
    g_tgtS[b * NG_ + n + 1] = make_float4(tx.y, ty.y, tz.y, tn1);
    float nht = mk.x + mk.y;

    float kld = 0.f;
    if (seg == 0) {
        float m_ = mu[b * L_ + tid], lv = logvar[b * L_ + tid];
        kld = 1.f + lv - m_ * m_ - __expf(lv);
    }

    nhp = blockReduceSum(nhp, shr);
    teh = blockReduceSum(teh, shr);
    nht = blockReduceSum(nht, shr);
    ent = blockReduceSum(ent, shr);
    kld = blockReduceSum(kld, shr);
    if (tid == 0) {
        atomicAdd(&g_bat[b * 4 + 0], nhp);
        atomicAdd(&g_bat[b * 4 + 1], teh);
        atomicAdd(&g_bat[b * 4 + 2], nht);
        atomicAdd(&g_acc[3], ent);
        atomicAdd(&g_acc[5], nht);
        if (seg == 0) atomicAdd(&g_acc[4], kld);
    }
}

// ---------------------------------------------------------------------------
// Fused chamfer: blocks [0,512) = pass1 (pred->tgt, argmin embedded),
//                blocks [512,1024) = pass2 (tgt->pred, min only).
// Each block: 1024 register points (4/thread), 256-wide reduction chunk in smem.
__global__ __launch_bounds__(256) void chamfer_kernel() {
    __shared__ ulonglong2 shA[128], shB[128];
    int blk = blockIdx.x, tid = threadIdx.x;
    bool isP1 = blk < 512;
    int w = isP1 ? blk : blk - 512;
    int b = w >> 4, sub = w & 15;
    int tile = sub >> 3;       // which 1024-point tile
    int chunk = sub & 7;       // which 256-wide reduction chunk

    if (tid < 128) {
        const float4* PA = isP1 ? g_tgtPA : g_predPA;
        const float4* PB = isP1 ? g_tgtPB : g_predPB;
        float4 a = PA[b * 1024 + chunk * 128 + tid];
        float4 v = PB[b * 1024 + chunk * 128 + tid];
        shA[tid] = *(ulonglong2*)&a;
        shB[tid] = *(ulonglong2*)&v;
    }
    __syncthreads();

    if (isP1) {
        int pbase = b * NP_ + tile * 1024 + tid;
        ull ax2[4], ay2[4], az2[4];
        #pragma unroll
        for (int i = 0; i < 4; i++) {
            float4 p = g_predS[pbase + i * 256];
            ax2[i] = dup2(p.x); ay2[i] = dup2(p.y); az2[i] = dup2(p.z);
        }
        float best[8];
        #pragma unroll
        for (int i = 0; i < 8; i++) best[i] = 3.4e38f;

        unsigned j2 = 0;
        #pragma unroll 2
        for (int j = 0; j < 128; j++) {
            ulonglong2 A = shA[j], Bv = shB[j];
            unsigned jlo = j2, jhi = j2 | 1u;
            #pragma unroll
            for (int i = 0; i < 4; i++) {
                ull t = fma2(az2[i], Bv.x, Bv.y);
                t = fma2(ay2[i], A.y, t);
                t = fma2(ax2[i], A.x, t);
                float2 v = unpack2(t);
                unsigned elo = (__float_as_uint(v.x) & 0xFFFFFF00u) | jlo;
                unsigned ehi = (__float_as_uint(v.y) & 0xFFFFFF00u) | jhi;
                best[2 * i]     = fminf(best[2 * i],     __uint_as_float(elo));
                best[2 * i + 1] = fminf(best[2 * i + 1], __uint_as_float(ehi));
            }
            j2 += 2;
        }
        #pragma unroll
        for (int i = 0; i < 4; i++)
            g_best1[chunk][pbase + i * 256] = fminf(best[2 * i], best[2 * i + 1]);
    } else {
        int tbase = b * NG_ + tile * 1024 + tid;
        ull tx2[4], ty2[4], tz2[4];
        #pragma unroll
        for (int i = 0; i < 4; i++) {
            float4 t = g_tgtS[tbase + i * 256];
            tx2[i] = dup2(t.x); ty2[i] = dup2(t.y); tz2[i] = dup2(t.z);
        }
        float bl[4], bh[4];
        #pragma unroll
        for (int i = 0; i < 4; i++) { bl[i] = 3.4e38f; bh[i] = 3.4e38f; }

        #pragma unroll 2
        for (int j = 0; j < 128; j++) {
            ulonglong2 A = shA[j], Bv = shB[j];
            #pragma unroll
            for (int i = 0; i < 4; i++) {
                ull t = fma2(tz2[i], Bv.x, Bv.y);
                t = fma2(ty2[i], A.y, t);
                t = fma2(tx2[i], A.x, t);
                float2 v = unpack2(t);
                bl[i] = fminf(bl[i], v.x);
                bh[i] = fminf(bh[i], v.y);
            }
        }
        #pragma unroll
        for (int i = 0; i < 4; i++)
            g_best2[chunk][tbase + i * 256] = fminf(bl[i], bh[i]);
    }
}

// ---------------------------------------------------------------------------
__global__ __launch_bounds__(256) void combine_kernel(
    const float* __restrict__ preds, const float* __restrict__ target,
    const float* __restrict__ mask) {
    __shared__ float shr[8];
    int blk = blockIdx.x, tid = threadIdx.x;

    if (blk < 128) {
        float md = 0.f, le = 0.f;
        #pragma unroll
        for (int r = 0; r < 2; r++) {
            int n = blk * 512 + r * 256 + tid;
            float best = g_best1[0][n];
            int sbest = 0;
            #pragma unroll
            for (int s = 1; s < 8; s++) {
                float v = g_best1[s][n];
                if (v < best) { best = v; sbest = s; }
            }
            int idx = sbest * 256 + (int)(__float_as_uint(best) & 0xFFu);
            int b = n >> 11, nn = n & (NP_ - 1);
            md += fmaxf(g_predS[n].w + best, 0.f);
            float tE = target[(size_t)b * 4 * NG_ + 3 * NG_ + idx];
            float pE = preds[(size_t)b * 5 * NP_ + 3 * NP_ + nn];
            le += fabsf(pE - tE);
        }
        md = blockReduceSum(md, shr);
        le = blockReduceSum(le, shr);
        if (tid == 0) { atomicAdd(&g_acc[0], md); atomicAdd(&g_acc[1], le); }
    } else {
        float s = 0.f;
        #pragma unroll
        for (int r = 0; r < 2; r++) {
            int m = (blk - 128) * 512 + r * 256 + tid;
            float best = g_best2[0][m];
            #pragma unroll
            for (int c = 1; c < 8; c++) best = fminf(best, g_best2[c][m]);
            s += fmaxf(g_tgtS[m].w + best, 0.f) * mask[m];
        }
        s = blockReduceSum(s, shr);
        if (tid == 0) atomicAdd(&g_acc[2], s);
    }
}

// ---------------------------------------------------------------------------
__global__ void final_kernel(const float* __restrict__ kl_weight,
                             const float* __restrict__ e_init,
                             float* __restrict__ out, int out_size) {
    int t = threadIdx.x;
    float dh2 = 0.f, de2 = 0.f;
    if (t < B_) {
        float nhp = g_bat[t * 4 + 0];
        float teh = g_bat[t * 4 + 1];
        float nht = g_bat[t * 4 + 2];
        float dh = nhp - nht;
        float de = teh - e_init[t];
        dh2 = dh * dh;
        de2 = de * de;
    }
    const unsigned full = 0xffffffffu;
    #pragma unroll
    for (int o = 16; o > 0; o >>= 1) {
        dh2 += __shfl_down_sync(full, dh2, o);
        de2 += __shfl_down_sync(full, de2, o);
    }
    if (t == 0) {
        float chamP = g_acc[0] / (float)(B_ * NP_);
        float chamT = g_acc[2] / g_acc[5];
        float loss_chamf = (chamT + chamP) * LAMBDA_CHAMFER;
        float localE = g_acc[1] / (float)(B_ * NP_);
        float ge   = LAMBDA_E_SUM * de2 / (float)B_;
        float hit  = LAMBDA_HIT   * dh2 / (float)B_;
        float entr = LAMBDA_HIT_ENTROPY * g_acc[3] / (float)(B_ * NP_);
        float kld  = kl_weight[0] * (-0.5f * g_acc[4] / (float)B_);
        float total = loss_chamf + localE + kld + ge + hit + entr;

        if (out_size >= 6) {
            out[0] = total;
            out[1] = loss_chamf;
            out[2] = localE;
            out[3] = ge;
            out[4] = hit;
            out[5] = kld;
        } else if (out_size == 5) {
            out[0] = loss_chamf; out[1] = localE; out[2] = ge;
            out[3] = hit;        out[4] = kld;
        } else {
            out[0] = total;
        }
    }
}

// ---------------------------------------------------------------------------
extern "C" void kernel_launch(void* const* d_in, const int* in_sizes, int n_in,
                              void* d_out, int out_size) {
    const float* preds  = (const float*)d_in[0];
    const float* target = (const float*)d_in[1];
    const float* tmask  = (const float*)d_in[2];
    const float* mu     = (const float*)d_in[3];
    const float* logvar = (const float*)d_in[4];
    const float* e_init = (const float*)d_in[5];
    const float* klw    = (const float*)d_in[6];
    float* out = (float*)d_out;

    init_kernel<<<1, 128>>>();
    prep_kernel<<<128, 256>>>(preds, target, tmask, mu, logvar);
    chamfer_kernel<<<1024, 256>>>();
    combine_kernel<<<256, 256>>>(preds, target, tmask);
    final_kernel<<<1, 32>>>(klw, e_init, out, out_size);
}

// round 4
// speedup vs baseline: 1.6899x; 1.1143x over previous
#include <cuda_runtime.h>
#include <math.h>

#define B_  32
#define NP_ 2048
#define NG_ 2048
#define L_  256
#define BIGF 1e18f
#define EPSF 1e-6f

#define LAMBDA_E_SUM       10.0f
#define LAMBDA_HIT         20.0f
#define LAMBDA_CHAMFER     0.001f
#define LAMBDA_HIT_ENTROPY 0.1f

typedef unsigned long long ull;

// ---------------- device scratch ----------------
// Packed pair layouts (pairs of adjacent points j, j+1):
//   PA[jp] = {c0_0,c0_1,c1_0,c1_1}  PB[jp] = {c2_0,c2_1,w_0,w_1}
// pred: c=-2*xyz, w=|p|^2 ; tgt: c=xyz, w=|t|^2 + BIG*!mask
__device__ float4 g_predPA[B_ * NP_ / 2];
__device__ float4 g_predPB[B_ * NP_ / 2];
__device__ float4 g_tgtPA [B_ * NG_ / 2];
__device__ float4 g_tgtPB [B_ * NG_ / 2];
__device__ float4 g_predS[B_ * NP_];   // {-2x,-2y,-2z, pn}
__device__ float4 g_tgtS [B_ * NG_];   // {  x,  y,  z, tn}
// Global minima via atomicMin on order-preserving encoded uints.
// g_min1 values carry the target index in low 11 mantissa bits.
__device__ unsigned g_min1[B_ * NP_];
__device__ unsigned g_min2[B_ * NG_];
// g_acc: 0 sum minD_pred  1 sum|dE|  2 sum minD_tgt*mask
__device__ float g_acc[4];
// per-(batch,seg) partials, race-free slots: [b*4+seg][nhp,teh,nht,ent,kld]
__device__ float g_bat[128][8];
__device__ unsigned g_ticket;

// ---------------------------------------------------------------------------
__device__ __forceinline__ ull fma2(ull a, ull b, ull c) {
    ull d;
    asm("fma.rn.f32x2 %0, %1, %2, %3;" : "=l"(d) : "l"(a), "l"(b), "l"(c));
    return d;
}
__device__ __forceinline__ ull dup2(float x) {
    ull d;
    asm("mov.b64 %0, {%1, %1};" : "=l"(d) : "f"(x));
    return d;
}
__device__ __forceinline__ float2 unpack2(ull v) {
    float2 r;
    asm("mov.b64 {%0, %1}, %2;" : "=f"(r.x), "=f"(r.y) : "l"(v));
    return r;
}
__device__ __forceinline__ unsigned encodeF(float f) {
    unsigned u = __float_as_uint(f);
    return u ^ ((unsigned)((int)u >> 31) | 0x80000000u);
}
__device__ __forceinline__ float decodeF(unsigned key, unsigned& raw) {
    unsigned m = (key & 0x80000000u) ? 0x80000000u : 0xFFFFFFFFu;
    raw = key ^ m;
    return __uint_as_float(raw);
}

__device__ __forceinline__ float blockReduceSum(float v, float* sh) {
    const unsigned full = 0xffffffffu;
    #pragma unroll
    for (int o = 16; o > 0; o >>= 1) v += __shfl_down_sync(full, v, o);
    int w = threadIdx.x >> 5, l = threadIdx.x & 31;
    __syncthreads();
    if (l == 0) sh[w] = v;
    __syncthreads();
    if (threadIdx.x < 32) {
        v = (threadIdx.x < (blockDim.x >> 5)) ? sh[threadIdx.x] : 0.0f;
        #pragma unroll
        for (int o = 16; o > 0; o >>= 1) v += __shfl_down_sync(full, v, o);
    }
    return v;
}

// ---------------------------------------------------------------------------
// 128 blocks: b = blk>>2, seg = blk&3 (256 packed pairs each). Also performs
// all per-launch initialization (g_min arrays, g_acc, ticket).
__global__ __launch_bounds__(256) void prep_kernel(
    const float* __restrict__ preds, const float* __restrict__ target,
    const float* __restrict__ mask,  const float* __restrict__ mu,
    const float* __restrict__ logvar) {
    __shared__ float shr[8];
    int blk = blockIdx.x, tid = threadIdx.x;
    int b = blk >> 2, seg = blk & 3;
    int jp = seg * 256 + tid;
    int n = 2 * jp;

    // init: 32768 threads, 65536 entries each array
    int gid = blk * 256 + tid;
    g_min1[2 * gid]     = 0xFFFFFFFFu;
    g_min1[2 * gid + 1] = 0xFFFFFFFFu;
    g_min2[2 * gid]     = 0xFFFFFFFFu;
    g_min2[2 * gid + 1] = 0xFFFFFFFFu;
    if (blk == 0 && tid < 4) g_acc[tid] = 0.0f;
    if (blk == 0 && tid == 4) g_ticket = 0u;

    const float* pb = preds  + (size_t)b * 5 * NP_;
    const float* tb = target + (size_t)b * 4 * NG_;
    const float* mb = mask   + (size_t)b * NG_;

    float2 x = *(const float2*)(pb + n);
    float2 y = *(const float2*)(pb + NP_ + n);
    float2 z = *(const float2*)(pb + 2 * NP_ + n);
    float2 E = *(const float2*)(pb + 3 * NP_ + n);
    float2 h = *(const float2*)(pb + 4 * NP_ + n);
    float pn0 = x.x * x.x + y.x * y.x + z.x * z.x;
    float pn1 = x.y * x.y + y.y * y.y + z.y * z.y;
    g_predPA[b * 1024 + jp] = make_float4(-2.f * x.x, -2.f * x.y, -2.f * y.x, -2.f * y.y);
    g_predPB[b * 1024 + jp] = make_float4(-2.f * z.x, -2.f * z.y, pn0, pn1);
    g_predS[b * NP_ + n]     = make_float4(-2.f * x.x, -2.f * y.x, -2.f * z.x, pn0);
    g_predS[b * NP_ + n + 1] = make_float4(-2.f * x.y, -2.f * y.y, -2.f * z.y, pn1);
    float nhp = h.x + h.y;
    float teh = E.x * h.x + E.y * h.y;
    float ent = -(h.x * __logf(h.x + EPSF) + (1.f - h.x) * __logf(1.f - h.x + EPSF))
                -(h.y * __logf(h.y + EPSF) + (1.f - h.y) * __logf(1.f - h.y + EPSF));

    float2 tx = *(const float2*)(tb + n);
    float2 ty = *(const float2*)(tb + NG_ + n);
    float2 tz = *(const float2*)(tb + 2 * NG_ + n);
    float2 mk = *(const float2*)(mb + n);
    float tn0 = tx.x * tx.x + ty.x * ty.x + tz.x * tz.x;
    float tn1 = tx.y * tx.y + ty.y * ty.y + tz.y * tz.y;
    g_tgtPA[b * 1024 + jp] = make_float4(tx.x, tx.y, ty.x, ty.y);
    g_tgtPB[b * 1024 + jp] = make_float4(tz.x, tz.y,
                                         tn0 + (mk.x == 0.f ? BIGF : 0.f),
                                         tn1 + (mk.y == 0.f ? BIGF : 0.f));
    g_tgtS[b * NG_ + n]     = make_float4(tx.x, ty.x, tz.x, tn0);
    g_tgtS[b * NG_ + n + 1] = make_float4(tx.y, ty.y, tz.y, tn1);
    float nht = mk.x + mk.y;

    float kld = 0.f;
    if (seg == 0) {
        float m_ = mu[b * L_ + tid], lv = logvar[b * L_ + tid];
        kld = 1.f + lv - m_ * m_ - __expf(lv);
    }

    nhp = blockReduceSum(nhp, shr);
    teh = blockReduceSum(teh, shr);
    nht = blockReduceSum(nht, shr);
    ent = blockReduceSum(ent, shr);
    kld = blockReduceSum(kld, shr);
    if (tid == 0) {
        float* s = g_bat[b * 4 + seg];
        s[0] = nhp; s[1] = teh; s[2] = nht; s[3] = ent; s[4] = kld;
    }
}

// ---------------------------------------------------------------------------
// Fused chamfer. 1024 blocks:
//   [0,512)   pass1: pred->tgt, argmin embedded in low 11 mantissa bits
//   [512,1024) pass2: tgt->pred, plain min
// Each block: all 2048 points of one batch (8/thread) x one 128-point chunk.
__global__ __launch_bounds__(256, 2) void chamfer_kernel() {
    __shared__ ulonglong2 shA[64], shB[64];
    int blk = blockIdx.x, tid = threadIdx.x;
    bool isP1 = blk < 512;
    int w = isP1 ? blk : blk - 512;
    int b = w >> 4, chunk = w & 15;

    if (tid < 64) {
        const float4* PA = isP1 ? g_tgtPA : g_predPA;
        const float4* PB = isP1 ? g_tgtPB : g_predPB;
        float4 a = PA[b * 1024 + chunk * 64 + tid];
        float4 v = PB[b * 1024 + chunk * 64 + tid];
        shA[tid] = *(ulonglong2*)&a;
        shB[tid] = *(ulonglong2*)&v;
    }
    __syncthreads();

    if (isP1) {
        int pbase = b * NP_ + tid;
        ull ax2[8], ay2[8], az2[8];
        #pragma unroll
        for (int i = 0; i < 8; i++) {
            float4 p = g_predS[pbase + i * 256];
            ax2[i] = dup2(p.x); ay2[i] = dup2(p.y); az2[i] = dup2(p.z);
        }
        float bl[8], bh[8];
        #pragma unroll
        for (int i = 0; i < 8; i++) { bl[i] = 3.4e38f; bh[i] = 3.4e38f; }

        unsigned jlo = (unsigned)(chunk * 128);
        #pragma unroll 4
        for (int j = 0; j < 64; j++) {
            ulonglong2 A = shA[j], Bv = shB[j];
            unsigned jhi = jlo | 1u;
            #pragma unroll
            for (int i = 0; i < 8; i++) {
                ull t = fma2(az2[i], Bv.x, Bv.y);
                t = fma2(ay2[i], A.y, t);
                t = fma2(ax2[i], A.x, t);
                float2 v = unpack2(t);
                unsigned elo = (__float_as_uint(v.x) & 0xFFFFF800u) | jlo;
                unsigned ehi = (__float_as_uint(v.y) & 0xFFFFF800u) | jhi;
                bl[i] = fminf(bl[i], __uint_as_float(elo));
                bh[i] = fminf(bh[i], __uint_as_float(ehi));
            }
            jlo += 2;
        }
        #pragma unroll
        for (int i = 0; i < 8; i++) {
            float m = fminf(bl[i], bh[i]);
            atomicMin(&g_min1[pbase + i * 256], encodeF(m));
        }
    } else {
        int tbase = b * NG_ + tid;
        ull tx2[8], ty2[8], tz2[8];
        #pragma unroll
        for (int i = 0; i < 8; i++) {
            float4 t = g_tgtS[tbase + i * 256];
            tx2[i] = dup2(t.x); ty2[i] = dup2(t.y); tz2[i] = dup2(t.z);
        }
        float bl[8], bh[8];
        #pragma unroll
        for (int i = 0; i < 8; i++) { bl[i] = 3.4e38f; bh[i] = 3.4e38f; }

        #pragma unroll 4
        for (int j = 0; j < 64; j++) {
            ulonglong2 A = shA[j], Bv = shB[j];
            #pragma unroll
            for (int i = 0; i < 8; i++) {
                ull t = fma2(tz2[i], Bv.x, Bv.y);
                t = fma2(ty2[i], A.y, t);
                t = fma2(tx2[i], A.x, t);
                float2 v = unpack2(t);
                bl[i] = fminf(bl[i], v.x);
                bh[i] = fminf(bh[i], v.y);
            }
        }
        #pragma unroll
        for (int i = 0; i < 8; i++) {
            float m = fminf(bl[i], bh[i]);
            atomicMin(&g_min2[tbase + i * 256], encodeF(m));
        }
    }
}

// ---------------------------------------------------------------------------
// Combine + final (ticket: last block computes the scalar losses).
__global__ __launch_bounds__(256) void combine_kernel(
    const float* __restrict__ preds, const float* __restrict__ target,
    const float* __restrict__ mask,  const float* __restrict__ e_init,
    const float* __restrict__ kl_weight, float* __restrict__ out, int out_size) {
    __shared__ float shr[8];
    __shared__ int s_last;
    int blk = blockIdx.x, tid = threadIdx.x;

    if (blk < 128) {
        float md = 0.f, le = 0.f;
        #pragma unroll
        for (int r = 0; r < 2; r++) {
            int n = blk * 512 + r * 256 + tid;
            unsigned raw;
            float best = decodeF(g_min1[n], raw);
            int idx = (int)(raw & 0x7FFu);
            int b = n >> 11, nn = n & (NP_ - 1);
            md += fmaxf(g_predS[n].w + best, 0.f);
            float tE = target[(size_t)b * 4 * NG_ + 3 * NG_ + idx];
            float pE = preds[(size_t)b * 5 * NP_ + 3 * NP_ + nn];
            le += fabsf(pE - tE);
        }
        md = blockReduceSum(md, shr);
        le = blockReduceSum(le, shr);
        if (tid == 0) { atomicAdd(&g_acc[0], md); atomicAdd(&g_acc[1], le); }
    } else {
        float s = 0.f;
        #pragma unroll
        for (int r = 0; r < 2; r++) {
            int m = (blk - 128) * 512 + r * 256 + tid;
            unsigned raw;
            float best = decodeF(g_min2[m], raw);
            s += fmaxf(g_tgtS[m].w + best, 0.f) * mask[m];
        }
        s = blockReduceSum(s, shr);
        if (tid == 0) atomicAdd(&g_acc[2], s);
    }

    // ticket: last block does the final scalar computation
    if (tid == 0) {
        __threadfence();
        unsigned t = atomicAdd(&g_ticket, 1u);
        s_last = (t == 255u);
    }
    __syncthreads();
    if (!s_last) return;

    int t = tid;
    float dh2 = 0.f, de2 = 0.f, ent = 0.f, kld = 0.f, nhtTot = 0.f;
    if (t < B_) {
        float nhp = 0.f, teh = 0.f, nht = 0.f;
        #pragma unroll
        for (int s2 = 0; s2 < 4; s2++) {
            const float* sb = g_bat[t * 4 + s2];
            nhp += sb[0]; teh += sb[1]; nht += sb[2];
            ent += sb[3]; kld += sb[4];
        }
        float dh = nhp - nht;
        float de = teh - e_init[t];
        dh2 = dh * dh; de2 = de * de; nhtTot = nht;
    }
    if (t < 32) {
        const unsigned full = 0xffffffffu;
        #pragma unroll
        for (int o = 16; o > 0; o >>= 1) {
            dh2 += __shfl_down_sync(full, dh2, o);
            de2 += __shfl_down_sync(full, de2, o);
            ent += __shfl_down_sync(full, ent, o);
            kld += __shfl_down_sync(full, kld, o);
            nhtTot += __shfl_down_sync(full, nhtTot, o);
        }
        if (t == 0) {
            float a0 = atomicAdd(&g_acc[0], 0.f);
            float a1 = atomicAdd(&g_acc[1], 0.f);
            float a2 = atomicAdd(&g_acc[2], 0.f);
            float chamP = a0 / (float)(B_ * NP_);
            float chamT = a2 / nhtTot;
            float loss_chamf = (chamT + chamP) * LAMBDA_CHAMFER;
            float localE = a1 / (float)(B_ * NP_);
            float ge   = LAMBDA_E_SUM * de2 / (float)B_;
            float hit  = LAMBDA_HIT   * dh2 / (float)B_;
            float entr = LAMBDA_HIT_ENTROPY * ent / (float)(B_ * NP_);
            float kl   = kl_weight[0] * (-0.5f * kld / (float)B_);
            float total = loss_chamf + localE + kl + ge + hit + entr;

            if (out_size >= 6) {
                out[0] = total;
                out[1] = loss_chamf;
                out[2] = localE;
                out[3] = ge;
                out[4] = hit;
                out[5] = kl;
            } else if (out_size == 5) {
                out[0] = loss_chamf; out[1] = localE; out[2] = ge;
                out[3] = hit;        out[4] = kl;
            } else {
                out[0] = total;
            }
        }
    }
}

// ---------------------------------------------------------------------------
extern "C" void kernel_launch(void* const* d_in, const int* in_sizes, int n_in,
                              void* d_out, int out_size) {
    const float* preds  = (const float*)d_in[0];
    const float* target = (const float*)d_in[1];
    const float* tmask  = (const float*)d_in[2];
    const float* mu     = (const float*)d_in[3];
    const float* logvar = (const float*)d_in[4];
    const float* e_init = (const float*)d_in[5];
    const float* klw    = (const float*)d_in[6];
    float* out = (float*)d_out;

    prep_kernel<<<128, 256>>>(preds, target, tmask, mu, logvar);
    chamfer_kernel<<<1024, 256>>>();
    combine_kernel<<<256, 256>>>(preds, target, tmask, e_init, klw, out, out_size);
}